// round 7
// baseline (speedup 1.0000x reference)
#include <cuda_runtime.h>
#include <cuda_bf16.h>

#define BDIM 256
#define NROWS 4096
#define DCOLS 8192
#define NPAIRS (NROWS / 2)         // 2048 static row-pairs
#define NBLOCKS 592                // 148 SMs x 4 CTAs, one persistent wave

__device__ float g_pair_partials[NPAIRS];  // zero-init; masked pairs never written
__device__ unsigned int g_row_counter;     // dynamic work queue head (pairs*2)
__device__ unsigned int g_done_count;      // last-block-done; self-resetting

__device__ __forceinline__ float smoothl1(float a, float b) {
    float d = a - b;
    float ad = fabsf(d);
    return (ad < 1.0f) ? (0.5f * d * d) : (ad - 0.5f);
}

// Per-thread partial over one row, 4-deep front-batched LDG.128.
__device__ __forceinline__ float row_partial(const float* __restrict__ in,
                                             const float* __restrict__ tgt,
                                             int row, int tid) {
    const float4* __restrict__ A =
        reinterpret_cast<const float4*>(in  + (size_t)row * DCOLS);
    const float4* __restrict__ B =
        reinterpret_cast<const float4*>(tgt + (size_t)row * DCOLS);

    float acc0 = 0.0f, acc1 = 0.0f;
    #pragma unroll
    for (int half = 0; half < 2; ++half) {
        float4 x[4], y[4];
        #pragma unroll
        for (int j = 0; j < 4; ++j) {
            int i = (half * 4 + j) * BDIM + tid;
            x[j] = A[i];
            y[j] = B[i];
        }
        #pragma unroll
        for (int j = 0; j < 4; ++j) {
            acc0 += smoothl1(x[j].x, y[j].x);
            acc1 += smoothl1(x[j].y, y[j].y);
            acc0 += smoothl1(x[j].z, y[j].z);
            acc1 += smoothl1(x[j].w, y[j].w);
        }
    }
    return acc0 + acc1;
}

__global__ __launch_bounds__(BDIM, 4)
void mask_smoothl1_dynamic_kernel(const float* __restrict__ in,
                                  const float* __restrict__ tgt,
                                  const int* __restrict__ mask,
                                  float* __restrict__ out) {
    const int tid = threadIdx.x;
    const int wid = tid >> 5;
    const int lid = tid & 31;

    __shared__ int s_row, s_m0, s_m1;
    __shared__ float warp_sums[BDIM / 32];

    while (true) {
        // thread 0: fetch next pair with at least one active row (no block sync
        // in the skip path — skips cost only thread-0 latency)
        if (tid == 0) {
            int r = -1, m0 = 0, m1 = 0;
            while (true) {
                unsigned int idx = atomicAdd(&g_row_counter, 2u);
                if (idx >= NROWS) break;
                int2 mm = reinterpret_cast<const int2*>(mask)[idx >> 1];
                if ((mm.x | mm.y) != 0) { r = (int)idx; m0 = mm.x; m1 = mm.y; break; }
            }
            s_row = r; s_m0 = m0; s_m1 = m1;
        }
        __syncthreads();

        const int row = s_row;
        const int m0 = s_m0, m1 = s_m1;
        if (row < 0) break;

        float acc = 0.0f;
        if (m0 != 0) acc += (float)m0 * row_partial(in, tgt, row,     tid);
        if (m1 != 0) acc += (float)m1 * row_partial(in, tgt, row + 1, tid);
        acc *= (1.0f / (float)DCOLS);

        // block reduce (fixed tree -> deterministic per pair)
        #pragma unroll
        for (int off = 16; off > 0; off >>= 1)
            acc += __shfl_xor_sync(0xFFFFFFFFu, acc, off);
        if (lid == 0) warp_sums[wid] = acc;
        __syncthreads();

        if (tid == 0) {
            float v = 0.0f;
            #pragma unroll
            for (int w = 0; w < BDIM / 32; ++w) v += warp_sums[w];
            g_pair_partials[row >> 1] = v;
        }
        __syncthreads();   // protect s_row / warp_sums before next fetch
    }

    // ---- last-block-done detection ----
    __shared__ bool s_is_last;
    if (tid == 0) {
        __threadfence();
        unsigned int prev = atomicAdd(&g_done_count, 1u);
        s_is_last = (prev == NBLOCKS - 1);
    }
    __syncthreads();
    if (!s_is_last) return;

    if (tid == 0) {                 // reset queue + done flag for next replay
        g_row_counter = 0;
        g_done_count = 0;
    }

    // ---- final deterministic reduce over 2048 pair partials (fixed order) ----
    float facc = 0.0f;
    #pragma unroll
    for (int it = 0; it < NPAIRS / BDIM; ++it)
        facc += g_pair_partials[it * BDIM + tid];

    #pragma unroll
    for (int off = 16; off > 0; off >>= 1)
        facc += __shfl_xor_sync(0xFFFFFFFFu, facc, off);

    __shared__ float fin_sums[BDIM / 32];
    if (lid == 0) fin_sums[wid] = facc;
    __syncthreads();

    if (wid == 0) {
        float v = (lid < BDIM / 32) ? fin_sums[lid] : 0.0f;
        #pragma unroll
        for (int off = 4; off > 0; off >>= 1)
            v += __shfl_xor_sync(0xFFFFFFFFu, v, off);
        if (lid == 0) out[0] = v;
    }
}

extern "C" void kernel_launch(void* const* d_in, const int* in_sizes, int n_in,
                              void* d_out, int out_size) {
    const float* inputs  = (const float*)d_in[0];
    const float* targets = (const float*)d_in[1];
    const int*   mask    = (const int*)d_in[2];
    float* out = (float*)d_out;

    mask_smoothl1_dynamic_kernel<<<NBLOCKS, BDIM>>>(inputs, targets, mask, out);
}